// round 15
// baseline (speedup 1.0000x reference)
#include <cuda_runtime.h>

// Problem constants (fixed by the reference setup_inputs)
#define B   16
#define C   85
#define H   128
#define W   128
#define HW  (H * W)        // 16384
#define NT  64             // targets per image
#define NC  80             // num classes = C - 5
#define NCH 81             // channels 4..84 (obj + cls)

#define BLOCKS       1152               // single wave at 8 blocks/SM
#define THREADS      256

// dynamic work: 8 queues, chunks of 512 f4 (two 256-f4 steps, 8 KB)
#define NQ           8
#define CHUNK_F4     512
#define CHUNKS_PER_Q 1296               // 8 * 1296 * 512 == 5,308,416 f4 exactly

#define CH_F4      (HW / 4)             // 4096 float4 per channel
#define PER_B_F4   (NCH * CH_F4)        // 331776 float4 per batch image (ch 4..84)

#define LOG2E      1.4426950408889634f
#define LN2        0.6931471805599453

// Global accumulators + work queues + completion counter. Zero at module load;
// the last block of every launch resets them, so every launch / replay is clean.
// [0] = sum log2(1+exp(x)) over obj channel        (softplus in log2 units)
// [1] = sum log2(1+exp(x)) over ALL channels 4..84 (cls = [1] - [0])
// [2] = sum (1 - iou) box loss
// [3] = obj correction: sum of raw x_obj at unique assigned cells
// [4] = cls correction: sum of raw x_cls at unique (cell, cls) pairs
__device__ double        g_acc[5];
__device__ unsigned int  g_work[NQ];
__device__ unsigned int  g_done;

__device__ __forceinline__ float ex2_approx(float x) {
    float r; asm("ex2.approx.f32 %0, %1;" : "=f"(r) : "f"(x)); return r;
}
__device__ __forceinline__ float lg2_approx(float x) {
    float r; asm("lg2.approx.f32 %0, %1;" : "=f"(r) : "f"(x)); return r;
}

// sum of log2(1+exp(x_i)) over a float4 with a single LG2:
// log2(prod (1 + 2^(x_i*log2e))).  Product <= (1+2^9)^4 ~ 2^36 — safe in fp32.
__device__ __forceinline__ float sp4_l2(float4 v) {
    const float u0 = ex2_approx(v.x * LOG2E);
    const float u1 = ex2_approx(v.y * LOG2E);
    const float u2 = ex2_approx(v.z * LOG2E);
    const float u3 = ex2_approx(v.w * LOG2E);
    return lg2_approx(((1.0f + u0) * (1.0f + u1)) * ((1.0f + u2) * (1.0f + u3)));
}

__global__ __launch_bounds__(THREADS, 8) void fused_kernel(const float* __restrict__ preds,
                                                           const float* __restrict__ tg,
                                                           float* __restrict__ out) {
    const int bid = blockIdx.x;
    const int tid = threadIdx.x;

    __shared__ float sh[THREADS];
    __shared__ float sh2[8];
    __shared__ int   s_key[NT];     // packed (idx<<7 | cls) per target

    const float4* __restrict__ p4 = reinterpret_cast<const float4*>(preds);

    float tot_acc = 0.0f;

    // ---------- special per-image work rides in the first 32 blocks ----------
    // Dynamic scheduling below absorbs the time these blocks spend here.

    // obj-channel sweep (blocks 16..31, image bid-16): re-reads 1 MB total
    // (~1.2% extra DRAM) so cls = total - obj at finalize.
    if (bid >= B && bid < 2 * B) {
        const int b = bid - B;
        const float4* __restrict__ po = p4 + ((size_t)b * C + 4) * CH_F4;

        float obj_acc = 0.0f;
#pragma unroll
        for (int i = 0; i < CH_F4 / THREADS; i++)          // 16 f4 per thread
            obj_acc += sp4_l2(po[tid + i * THREADS]);

        sh[tid] = obj_acc;
        __syncthreads();
#pragma unroll
        for (int s = THREADS / 2; s > 32; s >>= 1) {
            if (tid < s) sh[tid] += sh[tid + s];
            __syncthreads();
        }
        if (tid < 32) {
            float vo = sh[tid] + sh[tid + 32];
#pragma unroll
            for (int o = 16; o > 0; o >>= 1)
                vo += __shfl_down_sync(0xffffffffu, vo, o);
            if (tid == 0) atomicAdd(&g_acc[0], (double)vo);
        }
        __syncthreads();
    }

    // per-image target processing (blocks 0..15)
    if (bid < B) {
        const int b = bid;
        const int n = tid;

        float box_v = 0.0f, obj_v = 0.0f, cls_v = 0.0f;

        if (n < NT) {
            const float* t = tg + ((size_t)b * NT + n) * 5;
            const int   cls = (int)t[0];
            const float cx = t[1], cy = t[2];
            const int gi  = (int)(cx * (float)W);
            const int gj  = (int)(cy * (float)H);
            s_key[n] = ((gj * W + gi) << 7) | cls;
        }
        __syncthreads();

        if (n < NT) {
            const float* t = tg + ((size_t)b * NT + n) * 5;
            const int   cls = (int)t[0];
            const float cx = t[1], cy = t[2], w = t[3], h = t[4];
            const int   idx = s_key[n] >> 7;

            // set-scatter semantics: only the first target claiming a cell /
            // (cell,cls) contributes to the BCE correction term.
            bool first_obj = true, first_cls = true;
            for (int m = 0; m < n; m++) {
                if ((s_key[m] >> 7) == idx) {
                    first_obj = false;
                    if (s_key[m] == s_key[n]) first_cls = false;
                }
            }

            const float* pb = preds + (size_t)b * C * HW + idx;
            const float px = pb[0 * HW];
            const float py = pb[1 * HW];
            const float pw = pb[2 * HW];
            const float ph = pb[3 * HW];
            const float xo = pb[4 * HW];
            const float xc = pb[(size_t)(5 + cls) * HW];

            const float p1 = px - pw * 0.5f, pp2 = py - ph * 0.5f;
            const float p3 = px + pw * 0.5f, p4v = py + ph * 0.5f;
            const float g1 = (cx - w * 0.5f) * (float)W, g2 = (cy - h * 0.5f) * (float)H;
            const float g3 = (cx + w * 0.5f) * (float)W, g4 = (cy + h * 0.5f) * (float)H;

            const float ix1 = fmaxf(p1, g1), iy1 = fmaxf(pp2, g2);
            const float ix2 = fminf(p3, g3), iy2 = fminf(p4v, g4);
            const float inter = fmaxf(ix2 - ix1, 0.0f) * fmaxf(iy2 - iy1, 0.0f);
            const float a1 = (p3 - p1) * (p4v - pp2);
            const float a2 = (g3 - g1) * (g4 - g2);
            const float iou = inter / (a1 + a2 - inter + 1e-7f);

            box_v = 1.0f - iou;
            obj_v = first_obj ? xo : 0.0f;
            cls_v = first_cls ? xc : 0.0f;
        }

#pragma unroll
        for (int o = 16; o > 0; o >>= 1) {
            box_v += __shfl_down_sync(0xffffffffu, box_v, o);
            obj_v += __shfl_down_sync(0xffffffffu, obj_v, o);
            cls_v += __shfl_down_sync(0xffffffffu, cls_v, o);
        }
        if (n < NT && (n & 31) == 0) {
            sh2[(n >> 5) * 3 + 0] = box_v;
            sh2[(n >> 5) * 3 + 1] = obj_v;
            sh2[(n >> 5) * 3 + 2] = cls_v;
        }
        __syncthreads();
        if (tid == 0) {
            atomicAdd(&g_acc[2], (double)(sh2[0] + sh2[3]));
            atomicAdd(&g_acc[3], (double)(sh2[1] + sh2[4]));
            atomicAdd(&g_acc[4], (double)(sh2[2] + sh2[5]));
        }
        __syncthreads();
    }

    // ---------- bulk softplus sweep: dynamic work-stealing ----------
    // 8 queues, 1296 chunks each, chunk = 512 f4 (two coalesced 4 KB steps).
    // Next chunk id is fetched one ahead (thread 0 -> smem broadcast) so the
    // global-atomic latency overlaps chunk processing.
    const int q = bid & (NQ - 1);
    const int qbase = q * CHUNKS_PER_Q;

    __shared__ unsigned s_chunk;

    if (tid == 0) s_chunk = atomicAdd(&g_work[q], 1u);
    __syncthreads();
    unsigned c = s_chunk;

    while (c < CHUNKS_PER_Q) {
        __syncthreads();
        if (tid == 0) s_chunk = atomicAdd(&g_work[q], 1u);   // prefetch next

        const int f  = (qbase + (int)c) * CHUNK_F4;
        const int g0 = f + tid;
        const int g1 = f + THREADS + tid;
        const int b0 = g0 / PER_B_F4;                // const-div -> mul/shift
        const int b1 = g1 / PER_B_F4;
        // real addr: (b*C + 4)*CH_F4 + (g - b*PER_B_F4) == g + (b+1)*HW (f4)
        const float4 v0 = p4[g0 + (b0 + 1) * HW];
        const float4 v1 = p4[g1 + (b1 + 1) * HW];
        tot_acc += sp4_l2(v0) + sp4_l2(v1);

        __syncthreads();
        c = s_chunk;
    }

    // block reduce the total
    sh[tid] = tot_acc;
    __syncthreads();
#pragma unroll
    for (int s = THREADS / 2; s > 32; s >>= 1) {
        if (tid < s) sh[tid] += sh[tid + s];
        __syncthreads();
    }
    if (tid < 32) {
        float vt = sh[tid] + sh[tid + 32];
#pragma unroll
        for (int o = 16; o > 0; o >>= 1)
            vt += __shfl_down_sync(0xffffffffu, vt, o);
        if (tid == 0) atomicAdd(&g_acc[1], (double)vt);
    }

    // ---------- last-block-done finalize ----------
    __syncthreads();
    if (tid == 0) {
        __threadfence();
        unsigned int ticket = atomicAdd(&g_done, 1u);
        if (ticket == BLOCKS - 1) {
            // [0]=obj log2 sum, [1]=total log2 sum; cls = total - obj. Scale by ln2.
            const double sp_obj = LN2 * g_acc[0];
            const double sp_cls = LN2 * (g_acc[1] - g_acc[0]);
            const double obj_loss = (sp_obj - g_acc[3]) / (double)HW;
            const double cls_loss = (sp_cls - g_acc[4]) / ((double)HW * (double)NC);
            const double box_loss = g_acc[2];
            out[0] = (float)(0.05 * box_loss + 1.0 * obj_loss + 0.5 * cls_loss);
            // reset state for the next launch / graph replay
            g_acc[0] = 0.0; g_acc[1] = 0.0; g_acc[2] = 0.0;
            g_acc[3] = 0.0; g_acc[4] = 0.0;
#pragma unroll
            for (int i = 0; i < NQ; i++) g_work[i] = 0u;
            __threadfence();
            g_done = 0u;
        }
    }
}

extern "C" void kernel_launch(void* const* d_in, const int* in_sizes, int n_in,
                              void* d_out, int out_size) {
    const float* preds   = (const float*)d_in[0];
    const float* targets = (const float*)d_in[1];
    float* out = (float*)d_out;

    fused_kernel<<<BLOCKS, THREADS>>>(preds, targets, out);
}

// round 16
// speedup vs baseline: 1.2765x; 1.2765x over previous
#include <cuda_runtime.h>

// Problem constants (fixed by the reference setup_inputs)
#define B   16
#define C   85
#define H   128
#define W   128
#define HW  (H * W)        // 16384
#define NT  64             // targets per image
#define NC  80             // num classes = C - 5
#define NCH 81             // channels 4..84 (obj + cls)

#define BLOCKS     1152                 // single wave; 1152*256*18 == TOTAL_F4 exactly
#define THREADS    256
#define ITERS      18
#define STRIDE_F4  (BLOCKS * THREADS)   // 294912

#define CH_F4      (HW / 4)             // 4096 float4 per channel
#define PER_B_F4   (NCH * CH_F4)        // 331776 float4 per batch image (ch 4..84)

#define LOG2E      1.4426950408889634f
#define LN2        0.6931471805599453

// Global accumulators + completion counter. Zero at module load; the last
// block of every launch resets them, so each launch / graph replay starts clean.
// [0] = sum log2(1+exp(x)) over obj channel        (softplus in log2 units)
// [1] = sum log2(1+exp(x)) over ALL channels 4..84 (cls = [1] - [0])
// [2] = sum (1 - iou) box loss
// [3] = obj correction: sum of raw x_obj at unique assigned cells
// [4] = cls correction: sum of raw x_cls at unique (cell, cls) pairs
__device__ double        g_acc[5];
__device__ unsigned int  g_done;

__device__ __forceinline__ float ex2_approx(float x) {
    float r; asm("ex2.approx.f32 %0, %1;" : "=f"(r) : "f"(x)); return r;
}
__device__ __forceinline__ float lg2_approx(float x) {
    float r; asm("lg2.approx.f32 %0, %1;" : "=f"(r) : "f"(x)); return r;
}

// sum of log2(1+exp(x_i)) over a float4 with a single LG2:
// log2(prod (1 + 2^(x_i*log2e))).  Product <= (1+2^9)^4 ~ 2^36 — safe in fp32.
__device__ __forceinline__ float sp4_l2(float4 v) {
    const float u0 = ex2_approx(v.x * LOG2E);
    const float u1 = ex2_approx(v.y * LOG2E);
    const float u2 = ex2_approx(v.z * LOG2E);
    const float u3 = ex2_approx(v.w * LOG2E);
    return lg2_approx(((1.0f + u0) * (1.0f + u1)) * ((1.0f + u2) * (1.0f + u3)));
}

__global__ __launch_bounds__(THREADS, 8) void fused_kernel(const float* __restrict__ preds,
                                                           const float* __restrict__ tg,
                                                           float* __restrict__ out) {
    const int bid = blockIdx.x;
    const int tid = threadIdx.x;
    const int gid = bid * THREADS + tid;

    __shared__ float sh[THREADS];
    __shared__ float sh2[8];
    __shared__ int   s_key[NT];     // packed (idx<<7 | cls) per target

    // ---------- bulk softplus sweep: flat interleaved, one exact wave ----------
    // Loads paired back-to-back (MLP_p1 = 2) before the MUFU chains consume them.
    const float4* __restrict__ p4 = reinterpret_cast<const float4*>(preds);

    float tot_acc = 0.0f;

#pragma unroll
    for (int i = 0; i < ITERS; i += 2) {
        const int g0 = gid + i * STRIDE_F4;
        const int g1 = g0 + STRIDE_F4;
        const int b0 = g0 / PER_B_F4;                      // const-div -> mul/shift
        const int b1 = g1 / PER_B_F4;
        // real addr: (b*C + 4)*CH_F4 + (g - b*PER_B_F4)  ==  g + (b+1)*HW (f4 units)
        const float4 v0 = p4[g0 + (b0 + 1) * HW];
        const float4 v1 = p4[g1 + (b1 + 1) * HW];
        tot_acc += sp4_l2(v0);
        tot_acc += sp4_l2(v1);
    }

    // block reduce the total
    sh[tid] = tot_acc;
    __syncthreads();
#pragma unroll
    for (int s = THREADS / 2; s > 32; s >>= 1) {
        if (tid < s) sh[tid] += sh[tid + s];
        __syncthreads();
    }
    if (tid < 32) {
        float vt = sh[tid] + sh[tid + 32];
#pragma unroll
        for (int o = 16; o > 0; o >>= 1)
            vt += __shfl_down_sync(0xffffffffu, vt, o);
        if (tid == 0) atomicAdd(&g_acc[1], (double)vt);
    }
    __syncthreads();

    // ---------- obj-channel sweep (blocks 16..31, image bid-16) ----------
    // Re-reads 1 MB total (~1.2% extra DRAM); gives obj sum so cls = total - obj.
    if (bid >= B && bid < 2 * B) {
        const int b = bid - B;
        const float4* __restrict__ po = p4 + ((size_t)b * C + 4) * CH_F4;

        float obj_acc = 0.0f;
#pragma unroll
        for (int i = 0; i < CH_F4 / THREADS; i++)          // 16 f4 per thread
            obj_acc += sp4_l2(po[tid + i * THREADS]);

        sh[tid] = obj_acc;
        __syncthreads();
#pragma unroll
        for (int s = THREADS / 2; s > 32; s >>= 1) {
            if (tid < s) sh[tid] += sh[tid + s];
            __syncthreads();
        }
        if (tid < 32) {
            float vo = sh[tid] + sh[tid + 32];
#pragma unroll
            for (int o = 16; o > 0; o >>= 1)
                vo += __shfl_down_sync(0xffffffffu, vo, o);
            if (tid == 0) atomicAdd(&g_acc[0], (double)vo);
        }
    }

    // ---------- per-image target processing (rides in blocks 0..15) ----------
    if (bid < B) {
        const int b = bid;
        const int n = tid;

        float box_v = 0.0f, obj_v = 0.0f, cls_v = 0.0f;

        if (n < NT) {
            const float* t = tg + ((size_t)b * NT + n) * 5;
            const int   cls = (int)t[0];
            const float cx = t[1], cy = t[2];
            const int gi  = (int)(cx * (float)W);
            const int gj  = (int)(cy * (float)H);
            s_key[n] = ((gj * W + gi) << 7) | cls;
        }
        __syncthreads();

        if (n < NT) {
            const float* t = tg + ((size_t)b * NT + n) * 5;
            const int   cls = (int)t[0];
            const float cx = t[1], cy = t[2], w = t[3], h = t[4];
            const int   idx = s_key[n] >> 7;

            // set-scatter semantics: only the first target claiming a cell /
            // (cell,cls) contributes to the BCE correction term.
            bool first_obj = true, first_cls = true;
            for (int m = 0; m < n; m++) {
                if ((s_key[m] >> 7) == idx) {
                    first_obj = false;
                    if (s_key[m] == s_key[n]) first_cls = false;
                }
            }

            const float* pb = preds + (size_t)b * C * HW + idx;
            const float px = pb[0 * HW];
            const float py = pb[1 * HW];
            const float pw = pb[2 * HW];
            const float ph = pb[3 * HW];
            const float xo = pb[4 * HW];
            const float xc = pb[(size_t)(5 + cls) * HW];

            const float p1 = px - pw * 0.5f, pp2 = py - ph * 0.5f;
            const float p3 = px + pw * 0.5f, p4v = py + ph * 0.5f;
            const float g1 = (cx - w * 0.5f) * (float)W, g2 = (cy - h * 0.5f) * (float)H;
            const float g3 = (cx + w * 0.5f) * (float)W, g4 = (cy + h * 0.5f) * (float)H;

            const float ix1 = fmaxf(p1, g1), iy1 = fmaxf(pp2, g2);
            const float ix2 = fminf(p3, g3), iy2 = fminf(p4v, g4);
            const float inter = fmaxf(ix2 - ix1, 0.0f) * fmaxf(iy2 - iy1, 0.0f);
            const float a1 = (p3 - p1) * (p4v - pp2);
            const float a2 = (g3 - g1) * (g4 - g2);
            const float iou = inter / (a1 + a2 - inter + 1e-7f);

            box_v = 1.0f - iou;
            obj_v = first_obj ? xo : 0.0f;
            cls_v = first_cls ? xc : 0.0f;
        }

#pragma unroll
        for (int o = 16; o > 0; o >>= 1) {
            box_v += __shfl_down_sync(0xffffffffu, box_v, o);
            obj_v += __shfl_down_sync(0xffffffffu, obj_v, o);
            cls_v += __shfl_down_sync(0xffffffffu, cls_v, o);
        }
        if (n < NT && (n & 31) == 0) {
            sh2[(n >> 5) * 3 + 0] = box_v;
            sh2[(n >> 5) * 3 + 1] = obj_v;
            sh2[(n >> 5) * 3 + 2] = cls_v;
        }
        __syncthreads();
        if (tid == 0) {
            atomicAdd(&g_acc[2], (double)(sh2[0] + sh2[3]));
            atomicAdd(&g_acc[3], (double)(sh2[1] + sh2[4]));
            atomicAdd(&g_acc[4], (double)(sh2[2] + sh2[5]));
        }
    }

    // ---------- last-block-done finalize ----------
    __syncthreads();
    if (tid == 0) {
        __threadfence();
        unsigned int ticket = atomicAdd(&g_done, 1u);
        if (ticket == BLOCKS - 1) {
            // [0]=obj log2 sum, [1]=total log2 sum; cls = total - obj. Scale by ln2.
            const double sp_obj = LN2 * g_acc[0];
            const double sp_cls = LN2 * (g_acc[1] - g_acc[0]);
            const double obj_loss = (sp_obj - g_acc[3]) / (double)HW;
            const double cls_loss = (sp_cls - g_acc[4]) / ((double)HW * (double)NC);
            const double box_loss = g_acc[2];
            out[0] = (float)(0.05 * box_loss + 1.0 * obj_loss + 0.5 * cls_loss);
            // reset state for the next launch / graph replay
            g_acc[0] = 0.0; g_acc[1] = 0.0; g_acc[2] = 0.0;
            g_acc[3] = 0.0; g_acc[4] = 0.0;
            __threadfence();
            g_done = 0u;
        }
    }
}

extern "C" void kernel_launch(void* const* d_in, const int* in_sizes, int n_in,
                              void* d_out, int out_size) {
    const float* preds   = (const float*)d_in[0];
    const float* targets = (const float*)d_in[1];
    float* out = (float*)d_out;

    fused_kernel<<<BLOCKS, THREADS>>>(preds, targets, out);
}